// round 17
// baseline (speedup 1.0000x reference)
#include <cuda_runtime.h>
#include <cstdint>
#include <math.h>

#define S_LEN 2048
#define DM    2048
#define NH    16
#define NKV   4
#define HD    128

// ---------------- scratch (device globals; no runtime allocation) ----------------
__device__ float g_qlin[4096u * 2048u];   // roped Q, [B*S, NH*HD], tf32-rounded
__device__ float g_klin[4096u * 512u];    // roped K, [B*S, NKV*HD], tf32-rounded
__device__ float g_vlin[4096u * 512u];    // V,       [B*S, NKV*HD], tf32-rounded
__device__ float g_att[4096u * 2048u];    // attention out, tf32-rounded
// tf32-pre-rounded copies of GEMM inputs (cp.async + mma truncation == rna rounding)
__device__ float g_xr[4096u * 2048u];
__device__ float g_wq[2048u * 2048u];
__device__ float g_wk[2048u * 512u];
__device__ float g_wv[2048u * 512u];
__device__ float g_wo[2048u * 2048u];

// ---------------- helpers ----------------
__device__ __forceinline__ uint32_t f2tf32(float x) {
    uint32_t r;
    asm("cvt.rna.tf32.f32 %0, %1;" : "=r"(r) : "f"(x));
    return r;
}
__device__ __forceinline__ float f2tf32f(float x) { return __uint_as_float(f2tf32(x)); }

__device__ __forceinline__ void mma_tf32(float c[4], uint32_t a0, uint32_t a1,
                                         uint32_t a2, uint32_t a3,
                                         uint32_t b0, uint32_t b1) {
    asm volatile(
        "mma.sync.aligned.m16n8k8.row.col.f32.tf32.tf32.f32 "
        "{%0,%1,%2,%3}, {%4,%5,%6,%7}, {%8,%9}, {%0,%1,%2,%3};\n"
        : "+f"(c[0]), "+f"(c[1]), "+f"(c[2]), "+f"(c[3])
        : "r"(a0), "r"(a1), "r"(a2), "r"(a3), "r"(b0), "r"(b1));
}

__device__ __forceinline__ void cp16(float* smem_dst, const float* gmem_src) {
    uint32_t s = (uint32_t)__cvta_generic_to_shared(smem_dst);
    asm volatile("cp.async.cg.shared.global [%0], [%1], 16;\n" :: "r"(s), "l"(gmem_src));
}

// ---------------- fused tf32 pre-round over all 5 GEMM inputs ----------------
#define R_N0 2097152              // x    (4096*2048/4)
#define R_N1 (R_N0 + 1048576)     // + Wq (2048*2048/4)
#define R_N2 (R_N1 + 262144)      // + Wk
#define R_N3 (R_N2 + 262144)      // + Wv
#define R_N4 (R_N3 + 1048576)     // + Wo
__global__ void round_all(
    const float* __restrict__ x,  const float* __restrict__ Wq,
    const float* __restrict__ Wk, const float* __restrict__ Wv,
    const float* __restrict__ Wo,
    float* __restrict__ xr, float* __restrict__ wq, float* __restrict__ wk,
    float* __restrict__ wv, float* __restrict__ wo) {
    int i = blockIdx.x * blockDim.x + threadIdx.x;
    const float4* s; float4* d; int j;
    if (i < R_N0)      { s = (const float4*)x;  d = (float4*)xr; j = i; }
    else if (i < R_N1) { s = (const float4*)Wq; d = (float4*)wq; j = i - R_N0; }
    else if (i < R_N2) { s = (const float4*)Wk; d = (float4*)wk; j = i - R_N1; }
    else if (i < R_N3) { s = (const float4*)Wv; d = (float4*)wv; j = i - R_N2; }
    else if (i < R_N4) { s = (const float4*)Wo; d = (float4*)wo; j = i - R_N3; }
    else return;
    float4 v = s[j];
    v.x = f2tf32f(v.x); v.y = f2tf32f(v.y);
    v.z = f2tf32f(v.z); v.w = f2tf32f(v.w);
    d[j] = v;
}

// ---------------- TF32 GEMM body: C[128x128 tile] = A*B, cp.async double-buffered ----
// MODE: 0 = store raw fp32 (final output), 1 = rope + tf32 round, 2 = tf32 round.
#define GS_A   (128 * 36)
#define GS_B   (32 * 136)
#define GS_ST  (GS_A + GS_B)
#define GEMM_SMEM_BYTES (2 * GS_ST * 4)      // 71680

template<int MODE>
__device__ __forceinline__ void gemm_body(int N, int K,
    const float* __restrict__ A, const float* __restrict__ B, float* __restrict__ C,
    int bx, int by, float* sm,
    const float* __restrict__ cosv, const float* __restrict__ sinv) {
    const int tid  = threadIdx.x;
    const int lane = tid & 31, wid = tid >> 5;
    const int g = lane >> 2, t = lane & 3;
    const int wm = (wid >> 2) * 64, wn = (wid & 3) * 32;

    A += (size_t)by * 128 * K;
    B += (size_t)bx * 128;
    C += (size_t)by * 128 * N + (size_t)bx * 128;

    float acc[4][4][4];
#pragma unroll
    for (int mi = 0; mi < 4; mi++)
#pragma unroll
        for (int ni = 0; ni < 4; ni++)
#pragma unroll
            for (int r = 0; r < 4; r++) acc[mi][ni][r] = 0.f;

    const int niter = K >> 5;

    {
        float* As = sm; float* Bs = sm + GS_A;
#pragma unroll
        for (int it = 0; it < 4; it++) {
            int idx = tid + it * 256;
            int r = idx >> 3, c4 = (idx & 7) << 2;
            cp16(As + r * 36 + c4, A + (size_t)r * K + c4);
        }
#pragma unroll
        for (int it = 0; it < 4; it++) {
            int idx = tid + it * 256;
            int r = idx >> 5, c4 = (idx & 31) << 2;
            cp16(Bs + r * 136 + c4, B + (size_t)r * N + c4);
        }
        asm volatile("cp.async.commit_group;\n");
    }

    for (int i = 0; i < niter; i++) {
        float* As = sm + (i & 1) * GS_ST;
        float* Bs = As + GS_A;
        if (i + 1 < niter) {
            float* An = sm + ((i + 1) & 1) * GS_ST;
            float* Bn = An + GS_A;
            int k0 = (i + 1) << 5;
#pragma unroll
            for (int it = 0; it < 4; it++) {
                int idx = tid + it * 256;
                int r = idx >> 3, c4 = (idx & 7) << 2;
                cp16(An + r * 36 + c4, A + (size_t)r * K + k0 + c4);
            }
#pragma unroll
            for (int it = 0; it < 4; it++) {
                int idx = tid + it * 256;
                int r = idx >> 5, c4 = (idx & 31) << 2;
                cp16(Bn + r * 136 + c4, B + (size_t)(k0 + r) * N + c4);
            }
            asm volatile("cp.async.commit_group;\n");
            asm volatile("cp.async.wait_group 1;\n");
        } else {
            asm volatile("cp.async.wait_group 0;\n");
        }
        __syncthreads();

#pragma unroll
        for (int kk = 0; kk < 32; kk += 8) {
            uint32_t af[4][4], bf[4][2];
#pragma unroll
            for (int mi = 0; mi < 4; mi++) {
                const float* ar = As + (wm + mi * 16 + g) * 36 + kk + t;
                af[mi][0] = __float_as_uint(ar[0]);
                af[mi][1] = __float_as_uint(ar[8 * 36]);
                af[mi][2] = __float_as_uint(ar[4]);
                af[mi][3] = __float_as_uint(ar[8 * 36 + 4]);
            }
#pragma unroll
            for (int ni = 0; ni < 4; ni++) {
                const float* br = Bs + (kk + t) * 136 + wn + ni * 8 + g;
                bf[ni][0] = __float_as_uint(br[0]);
                bf[ni][1] = __float_as_uint(br[4 * 136]);
            }
#pragma unroll
            for (int mi = 0; mi < 4; mi++)
#pragma unroll
                for (int ni = 0; ni < 4; ni++)
                    mma_tf32(acc[mi][ni], af[mi][0], af[mi][1], af[mi][2], af[mi][3],
                             bf[ni][0], bf[ni][1]);
        }
        __syncthreads();
    }

    // epilogue
#pragma unroll
    for (int mi = 0; mi < 4; mi++) {
        const int row = wm + mi * 16 + g;
#pragma unroll
        for (int ni = 0; ni < 4; ni++) {
            const int col = wn + ni * 8 + 2 * t;
            float v0 = acc[mi][ni][0], v1 = acc[mi][ni][1];
            float v2 = acc[mi][ni][2], v3 = acc[mi][ni][3];
            if (MODE == 1) {
                // rope: (v0,v1) even/odd pair at head-dim pair i, seq pos s
                const int i = (wn >> 1) + ni * 4 + t;    // (col%128)/2, col<128 in tile
                const int s0 = (by * 128 + row) & (S_LEN - 1);
                const int s1 = s0 + 8;                   // same batch (tile-aligned)
                float c0 = cosv[s0 * 64 + i], n0 = sinv[s0 * 64 + i];
                float c1 = cosv[s1 * 64 + i], n1 = sinv[s1 * 64 + i];
                float r0 = v0 * c0 - v1 * n0, r1 = v0 * n0 + v1 * c0;
                float r2 = v2 * c1 - v3 * n1, r3 = v2 * n1 + v3 * c1;
                v0 = f2tf32f(r0); v1 = f2tf32f(r1);
                v2 = f2tf32f(r2); v3 = f2tf32f(r3);
            } else if (MODE == 2) {
                v0 = f2tf32f(v0); v1 = f2tf32f(v1);
                v2 = f2tf32f(v2); v3 = f2tf32f(v3);
            }
            *(float2*)(C + (size_t)row * N + col)       = make_float2(v0, v1);
            *(float2*)(C + (size_t)(row + 8) * N + col) = make_float2(v2, v3);
        }
    }
}

// Merged QKV projection + fused rope/round epilogue.
// grid.x = 24 (16 Wq tiles + 4 Wk + 4 Wv), grid.y = 32.
__global__ __launch_bounds__(256, 2) void qkv_gemm(
    const float* __restrict__ x,
    const float* __restrict__ Wq, const float* __restrict__ Wk, const float* __restrict__ Wv,
    float* __restrict__ qlin, float* __restrict__ klin, float* __restrict__ vlin,
    const float* __restrict__ cosv, const float* __restrict__ sinv) {
    extern __shared__ float sm[];
    int bx = blockIdx.x;
    if (bx < 16)
        gemm_body<1>(2048, 2048, x, Wq, qlin, bx, blockIdx.y, sm, cosv, sinv);
    else if (bx < 20)
        gemm_body<1>(512, 2048, x, Wk, klin, bx - 16, blockIdx.y, sm, cosv, sinv);
    else
        gemm_body<2>(512, 2048, x, Wv, vlin, bx - 20, blockIdx.y, sm, cosv, sinv);
}

__global__ __launch_bounds__(256, 2) void out_gemm(
    const float* __restrict__ A, const float* __restrict__ B, float* __restrict__ C) {
    extern __shared__ float sm[];
    gemm_body<0>(2048, 2048, A, B, C, blockIdx.x, blockIdx.y, sm, nullptr, nullptr);
}

// ---------------- TF32 tensor-core flash attention (causal, GQA) ----------------
// BQ=128, BK=64, 2-stage cp.async K/V pipeline; P in registers via shfl-transpose.
// Reads Q/K/V directly from projection layouts (row strides DM / 512).
#define AQ_STR 132
#define VS_STR 136
#define ATT_SMEM_FLOATS (128*AQ_STR + 2*64*AQ_STR + 2*64*VS_STR)
#define KV_STRIDE (NKV * HD)    // 512

__global__ __launch_bounds__(256) void attn_tf32(const float* __restrict__ Q,
    const float* __restrict__ K, const float* __restrict__ V, float* __restrict__ Out) {
    extern __shared__ float smf[];
    float* Qs = smf;                         // [128][132]
    float* Ks = Qs + 128 * AQ_STR;           // 2 stages [64][132]
    float* Vs = Ks + 2 * 64 * AQ_STR;        // 2 stages [64][136]

    const int qt = (int)gridDim.x - 1 - (int)blockIdx.x;  // heavy tiles first
    const int h  = blockIdx.y;
    const int b  = blockIdx.z;
    const int kvh = h >> 2;
    const int tid = threadIdx.x;
    const int lane = tid & 31, w = tid >> 5;
    const int g = lane >> 2, t = lane & 3;
    const float scale = 0.08838834764831845f;

    const int src0 = (lane & ~3) | (t >> 1);
    const int src2 = src0 + 2;
    const bool todd = (t & 1);

    // strided views into projection outputs
    const float* Qg = Q + ((size_t)(b * S_LEN + qt * 128)) * DM + h * HD;
    const float* Kg = K + ((size_t)(b * S_LEN)) * KV_STRIDE + kvh * HD;
    const float* Vg = V + ((size_t)(b * S_LEN)) * KV_STRIDE + kvh * HD;

    // prologue: Q tile + K/V stage 0, one cp.async group
#pragma unroll
    for (int it = 0; it < 16; it++) {
        int i4 = tid + it * 256;
        int r = i4 >> 5, c = (i4 & 31) << 2;
        cp16(Qs + r * AQ_STR + c, Qg + (size_t)r * DM + c);
    }
#pragma unroll
    for (int it = 0; it < 8; it++) {
        int i4 = tid + it * 256;
        int r = i4 >> 5, c = (i4 & 31) << 2;
        cp16(Ks + r * AQ_STR + c, Kg + (size_t)r * KV_STRIDE + c);
        cp16(Vs + r * VS_STR + c, Vg + (size_t)r * KV_STRIDE + c);
    }
    asm volatile("cp.async.commit_group;\n");

    float o[16][4];
#pragma unroll
    for (int ni = 0; ni < 16; ni++)
#pragma unroll
        for (int r = 0; r < 4; r++) o[ni][r] = 0.f;

    float m0 = -1e30f, m1 = -1e30f, l0 = 0.f, l1 = 0.f;
    const int q0 = qt * 128 + w * 16 + g;
    const int q1 = q0 + 8;

    const int nkt = 2 * qt + 2;
    for (int kt = 0; kt < nkt; kt++) {
        float* Kst = Ks + (kt & 1) * 64 * AQ_STR;
        float* Vst = Vs + (kt & 1) * 64 * VS_STR;
        if (kt + 1 < nkt) {
            float* Kn = Ks + ((kt + 1) & 1) * 64 * AQ_STR;
            float* Vn = Vs + ((kt + 1) & 1) * 64 * VS_STR;
            const float* Kgn = Kg + (size_t)(kt + 1) * 64 * KV_STRIDE;
            const float* Vgn = Vg + (size_t)(kt + 1) * 64 * KV_STRIDE;
#pragma unroll
            for (int it = 0; it < 8; it++) {
                int i4 = tid + it * 256;
                int r = i4 >> 5, c = (i4 & 31) << 2;
                cp16(Kn + r * AQ_STR + c, Kgn + (size_t)r * KV_STRIDE + c);
                cp16(Vn + r * VS_STR + c, Vgn + (size_t)r * KV_STRIDE + c);
            }
            asm volatile("cp.async.commit_group;\n");
            asm volatile("cp.async.wait_group 1;\n");
        } else {
            asm volatile("cp.async.wait_group 0;\n");
        }
        __syncthreads();

        // ---- S = Q K^T : warp computes 16x64 ----
        float sfr[8][4];
#pragma unroll
        for (int ni = 0; ni < 8; ni++)
#pragma unroll
            for (int r = 0; r < 4; r++) sfr[ni][r] = 0.f;

#pragma unroll
        for (int kk = 0; kk < 16; kk++) {
            const float* qr = Qs + (w * 16 + g) * AQ_STR + kk * 8 + t;
            uint32_t a0 = __float_as_uint(qr[0]);
            uint32_t a1 = __float_as_uint(qr[8 * AQ_STR]);
            uint32_t a2 = __float_as_uint(qr[4]);
            uint32_t a3 = __float_as_uint(qr[8 * AQ_STR + 4]);
#pragma unroll
            for (int ni = 0; ni < 8; ni++) {
                const float* kr = Kst + (ni * 8 + g) * AQ_STR + kk * 8 + t;
                mma_tf32(sfr[ni], a0, a1, a2, a3,
                         __float_as_uint(kr[0]), __float_as_uint(kr[4]));
            }
        }

        // ---- mask + scale ----
        const bool nm = (kt >= 2 * qt);
#pragma unroll
        for (int ni = 0; ni < 8; ni++) {
            int kb = kt * 64 + ni * 8 + 2 * t;
            float s0 = sfr[ni][0] * scale, s1 = sfr[ni][1] * scale;
            float s2 = sfr[ni][2] * scale, s3 = sfr[ni][3] * scale;
            if (nm) {
                if (kb     > q0) s0 = -1e30f;
                if (kb + 1 > q0) s1 = -1e30f;
                if (kb     > q1) s2 = -1e30f;
                if (kb + 1 > q1) s3 = -1e30f;
            }
            sfr[ni][0] = s0; sfr[ni][1] = s1; sfr[ni][2] = s2; sfr[ni][3] = s3;
        }

        // ---- online softmax ----
        float mn0 = -1e30f, mn1 = -1e30f;
#pragma unroll
        for (int ni = 0; ni < 8; ni++) {
            mn0 = fmaxf(mn0, fmaxf(sfr[ni][0], sfr[ni][1]));
            mn1 = fmaxf(mn1, fmaxf(sfr[ni][2], sfr[ni][3]));
        }
        mn0 = fmaxf(mn0, __shfl_xor_sync(0xffffffffu, mn0, 1));
        mn0 = fmaxf(mn0, __shfl_xor_sync(0xffffffffu, mn0, 2));
        mn1 = fmaxf(mn1, __shfl_xor_sync(0xffffffffu, mn1, 1));
        mn1 = fmaxf(mn1, __shfl_xor_sync(0xffffffffu, mn1, 2));

        float nmx0 = fmaxf(m0, mn0), nmx1 = fmaxf(m1, mn1);
        float al0 = __expf(m0 - nmx0), al1 = __expf(m1 - nmx1);
        m0 = nmx0; m1 = nmx1;

        float sum0 = 0.f, sum1 = 0.f;
#pragma unroll
        for (int ni = 0; ni < 8; ni++) {
            float p0 = __expf(sfr[ni][0] - m0);
            float p1 = __expf(sfr[ni][1] - m0);
            float p2 = __expf(sfr[ni][2] - m1);
            float p3 = __expf(sfr[ni][3] - m1);
            sum0 += p0 + p1; sum1 += p2 + p3;
            sfr[ni][0] = f2tf32f(p0);
            sfr[ni][1] = f2tf32f(p1);
            sfr[ni][2] = f2tf32f(p2);
            sfr[ni][3] = f2tf32f(p3);
        }
        sum0 += __shfl_xor_sync(0xffffffffu, sum0, 1);
        sum0 += __shfl_xor_sync(0xffffffffu, sum0, 2);
        sum1 += __shfl_xor_sync(0xffffffffu, sum1, 1);
        sum1 += __shfl_xor_sync(0xffffffffu, sum1, 2);
        l0 = l0 * al0 + sum0;
        l1 = l1 * al1 + sum1;

#pragma unroll
        for (int ni = 0; ni < 16; ni++) {
            o[ni][0] *= al0; o[ni][1] *= al0;
            o[ni][2] *= al1; o[ni][3] *= al1;
        }

        // ---- O += P V : shfl-transpose P frags, then mma ----
#pragma unroll
        for (int kk = 0; kk < 8; kk++) {
            float c0s0 = __shfl_sync(0xffffffffu, sfr[kk][0], src0);
            float c1s0 = __shfl_sync(0xffffffffu, sfr[kk][1], src0);
            float c2s0 = __shfl_sync(0xffffffffu, sfr[kk][2], src0);
            float c3s0 = __shfl_sync(0xffffffffu, sfr[kk][3], src0);
            float c0s2 = __shfl_sync(0xffffffffu, sfr[kk][0], src2);
            float c1s2 = __shfl_sync(0xffffffffu, sfr[kk][1], src2);
            float c2s2 = __shfl_sync(0xffffffffu, sfr[kk][2], src2);
            float c3s2 = __shfl_sync(0xffffffffu, sfr[kk][3], src2);
            uint32_t a0 = __float_as_uint(todd ? c1s0 : c0s0);
            uint32_t a1 = __float_as_uint(todd ? c3s0 : c2s0);
            uint32_t a2 = __float_as_uint(todd ? c1s2 : c0s2);
            uint32_t a3 = __float_as_uint(todd ? c3s2 : c2s2);
#pragma unroll
            for (int ni = 0; ni < 16; ni++) {
                const float* vr = Vst + (kk * 8 + t) * VS_STR + ni * 8 + g;
                mma_tf32(o[ni], a0, a1, a2, a3,
                         __float_as_uint(vr[0]), __float_as_uint(vr[4 * VS_STR]));
            }
        }
        __syncthreads();
    }

    // epilogue: rna-round outputs so the Wo GEMM's truncation is lossless
    float inv0 = 1.f / l0, inv1 = 1.f / l1;
    size_t ro0 = ((size_t)(b * S_LEN) + q0) * DM + h * HD;
    size_t ro1 = ((size_t)(b * S_LEN) + q1) * DM + h * HD;
#pragma unroll
    for (int ni = 0; ni < 16; ni++) {
        int c = ni * 8 + 2 * t;
        *(float2*)(Out + ro0 + c) =
            make_float2(f2tf32f(o[ni][0] * inv0), f2tf32f(o[ni][1] * inv0));
        *(float2*)(Out + ro1 + c) =
            make_float2(f2tf32f(o[ni][2] * inv1), f2tf32f(o[ni][3] * inv1));
    }
}

// ---------------- launch ----------------
extern "C" void kernel_launch(void* const* d_in, const int* in_sizes, int n_in,
                              void* d_out, int out_size) {
    const float* x  = (const float*)d_in[0];
    const float* rc = (const float*)d_in[1];
    const float* rs = (const float*)d_in[2];
    const float* Wq = (const float*)d_in[3];
    const float* Wk = (const float*)d_in[4];
    const float* Wv = (const float*)d_in[5];
    const float* Wo = (const float*)d_in[6];
    float* out = (float*)d_out;

    float *qlin, *klin, *vlin, *att;
    float *xr, *wq, *wk, *wv, *wo;
    cudaGetSymbolAddress((void**)&qlin, g_qlin);
    cudaGetSymbolAddress((void**)&klin, g_klin);
    cudaGetSymbolAddress((void**)&vlin, g_vlin);
    cudaGetSymbolAddress((void**)&att,  g_att);
    cudaGetSymbolAddress((void**)&xr,   g_xr);
    cudaGetSymbolAddress((void**)&wq,   g_wq);
    cudaGetSymbolAddress((void**)&wk,   g_wk);
    cudaGetSymbolAddress((void**)&wv,   g_wv);
    cudaGetSymbolAddress((void**)&wo,   g_wo);

    const int ATT_SMEM = ATT_SMEM_FLOATS * 4;   // 200 KB
    cudaFuncSetAttribute(attn_tf32, cudaFuncAttributeMaxDynamicSharedMemorySize, ATT_SMEM);
    cudaFuncSetAttribute(qkv_gemm, cudaFuncAttributeMaxDynamicSharedMemorySize, GEMM_SMEM_BYTES);
    cudaFuncSetAttribute(out_gemm, cudaFuncAttributeMaxDynamicSharedMemorySize, GEMM_SMEM_BYTES);

    // fused tf32 pre-round of all GEMM inputs (one launch)
    round_all<<<(R_N4 + 255) / 256, 256>>>(x, Wq, Wk, Wv, Wo, xr, wq, wk, wv, wo);

    // merged QKV projection with fused rope/round epilogue
    qkv_gemm<<<dim3(24, 32), 256, GEMM_SMEM_BYTES>>>(xr, wq, wk, wv,
                                                     qlin, klin, vlin, rc, rs);

    // attention (TF32 tensor cores, BK=64, 2-stage cp.async, shfl-transposed P,
    // strided reads directly from projection layouts)
    attn_tf32<<<dim3(S_LEN / 128, NH, 2), 256, ATT_SMEM>>>(qlin, klin, vlin, att);

    // output projection
    out_gemm<<<dim3(16, 32), 256, GEMM_SMEM_BYTES>>>(att, wo, out);
}